// round 1
// baseline (speedup 1.0000x reference)
#include <cuda_runtime.h>
#include <cuda_bf16.h>

#define N_NODES 100000
#define B_DIM   16

// Scratch: transposed x and accumulator, [N, B] layout so one edge's 16
// batch lanes are 64 contiguous bytes (2 L2 sectors).
__device__ float g_xt[N_NODES * B_DIM];
__device__ float g_yt[N_NODES * B_DIM];

// ---------------------------------------------------------------------------
// Kernel 1: transpose x [B,N] -> g_xt [N,B], and zero g_yt.
// Tile 16n x 16b through smem so both sides are coalesced.
// ---------------------------------------------------------------------------
__global__ void transpose_zero_kernel(const float* __restrict__ x, int N) {
    __shared__ float tile[16][17];
    int n0 = blockIdx.x * 16;
    int tx = threadIdx.x;      // 0..15
    int ty = threadIdx.y;      // 0..15

    // load: row b=ty, cols n0+tx  (coalesced along n)
    int n_l = n0 + tx;
    float v = 0.0f;
    if (n_l < N) v = x[ty * N + n_l];
    tile[ty][tx] = v;
    __syncthreads();

    // store: node n0+ty, batch tx  (coalesced: consecutive tx -> consecutive addr)
    int n_s = n0 + ty;
    if (n_s < N) {
        g_xt[n_s * B_DIM + tx] = tile[tx][ty];
        g_yt[n_s * B_DIM + tx] = 0.0f;
    }
}

// ---------------------------------------------------------------------------
// Kernel 2: edge stage. One thread per (edge, batch).
// lin = w*x_src + b ; m = (1-a)*lin + a*tanh(lin) ; atomicAdd to g_yt[dst].
// ---------------------------------------------------------------------------
__global__ void edge_kernel(const int*   __restrict__ src_idx,
                            const int*   __restrict__ dst_idx,
                            const float* __restrict__ edge_alpha,
                            const float* __restrict__ edge_w,
                            const float* __restrict__ edge_b,
                            int E) {
    int t = blockIdx.x * blockDim.x + threadIdx.x;
    if (t >= E * B_DIM) return;
    int e = t >> 4;
    int b = t & 15;

    int   s  = src_idx[e];
    int   d  = dst_idx[e];
    float w  = edge_w[e];
    float bb = edge_b[e];
    float a  = edge_alpha[e];

    float xv  = g_xt[s * B_DIM + b];
    float lin = fmaf(w, xv, bb);
    float th;
    asm("tanh.approx.f32 %0, %1;" : "=f"(th) : "f"(lin));
    float m = fmaf(a, th - lin, lin);   // (1-a)*lin + a*tanh(lin)

    atomicAdd(&g_yt[d * B_DIM + b], m);
}

// ---------------------------------------------------------------------------
// Kernel 3: node stage + transpose back. Reads g_yt [N,B] coalesced,
// applies node nonlinearity, writes out [B,N] coalesced via smem tile.
// ---------------------------------------------------------------------------
__global__ void node_kernel(const float* __restrict__ node_alpha,
                            const float* __restrict__ node_w,
                            const float* __restrict__ node_b,
                            float* __restrict__ out, int N) {
    __shared__ float tile[16][17];
    int n0 = blockIdx.x * 16;
    int tx = threadIdx.x;
    int ty = threadIdx.y;

    // load: node n0+ty, batch tx (coalesced)
    int n_l = n0 + ty;
    float v = 0.0f;
    if (n_l < N) v = g_yt[n_l * B_DIM + tx];
    tile[ty][tx] = v;
    __syncthreads();

    // store: batch ty, nodes n0+tx (coalesced along n)
    int n_s = n0 + tx;
    if (n_s < N) {
        float y   = tile[tx][ty];
        float w   = node_w[n_s];
        float bb  = node_b[n_s];
        float a   = node_alpha[n_s];
        float lin = fmaf(w, y, bb);
        float th;
        asm("tanh.approx.f32 %0, %1;" : "=f"(th) : "f"(lin));
        out[ty * N + n_s] = fmaf(a, th - lin, lin);
    }
}

// ---------------------------------------------------------------------------
// Input order (setup_inputs): x, src_idx, dst_idx, edge_alpha, edge_w,
// edge_b, node_alpha, node_w, node_b. Output: float32 [B, N].
// ---------------------------------------------------------------------------
extern "C" void kernel_launch(void* const* d_in, const int* in_sizes, int n_in,
                              void* d_out, int out_size) {
    const float* x          = (const float*)d_in[0];
    const int*   src_idx    = (const int*)  d_in[1];
    const int*   dst_idx    = (const int*)  d_in[2];
    const float* edge_alpha = (const float*)d_in[3];
    const float* edge_w     = (const float*)d_in[4];
    const float* edge_b     = (const float*)d_in[5];
    const float* node_alpha = (const float*)d_in[6];
    const float* node_w     = (const float*)d_in[7];
    const float* node_b     = (const float*)d_in[8];
    float* out = (float*)d_out;

    const int E = in_sizes[1];
    const int N = in_sizes[6];

    dim3 tb(16, 16);
    int n_tiles = (N + 15) / 16;

    transpose_zero_kernel<<<n_tiles, tb>>>(x, N);

    int total = E * B_DIM;
    int blocks = (total + 255) / 256;
    edge_kernel<<<blocks, 256>>>(src_idx, dst_idx, edge_alpha, edge_w, edge_b, E);

    node_kernel<<<n_tiles, tb>>>(node_alpha, node_w, node_b, out, N);
}

// round 2
// speedup vs baseline: 2.7206x; 2.7206x over previous
#include <cuda_runtime.h>
#include <cuda_bf16.h>

#define N_NODES 100000
#define B_DIM   16

// Scratch: transposed x and accumulator, [N, B] layout so one edge's 16
// batch lanes are 64 contiguous bytes.
__device__ float g_xt[N_NODES * B_DIM];
__device__ float g_yt[N_NODES * B_DIM];

// ---------------------------------------------------------------------------
// Kernel 1: transpose x [B,N] -> g_xt [N,B] (float4 tiles), zero g_yt.
// Tile: 64 nodes x 16 batches per block (256 threads).
// ---------------------------------------------------------------------------
__global__ void transpose_zero_kernel(const float* __restrict__ x, int N) {
    __shared__ float tile[16][67];   // stride 67 to limit bank conflicts
    int n0 = blockIdx.x * 64;
    int tid = threadIdx.x;           // 0..255

    // Load: 4 passes, each covers 4 batch rows x 64 nodes, coalesced along n.
    #pragma unroll
    for (int p = 0; p < 4; p++) {
        int b = p * 4 + (tid >> 6);      // 0..15
        int n = tid & 63;
        int nn = n0 + n;
        tile[b][n] = (nn < N) ? x[b * N + nn] : 0.0f;
    }
    __syncthreads();

    // Store: thread -> (node, batch-quad). Writes float4, fully coalesced.
    int n = tid >> 2;        // 0..63
    int q = tid & 3;         // 0..3
    int nn = n0 + n;
    if (nn < N) {
        float4 v;
        v.x = tile[4 * q + 0][n];
        v.y = tile[4 * q + 1][n];
        v.z = tile[4 * q + 2][n];
        v.w = tile[4 * q + 3][n];
        *(float4*)&g_xt[nn * B_DIM + 4 * q] = v;
        *(float4*)&g_yt[nn * B_DIM + 4 * q] = make_float4(0.f, 0.f, 0.f, 0.f);
    }
}

// ---------------------------------------------------------------------------
// Kernel 2: edge stage. One thread per (edge, batch-quad).
// float4 gather, 4x (fma, tanh, blend), ONE red.global.add.v4.f32.
// ---------------------------------------------------------------------------
__global__ void edge_kernel(const int*   __restrict__ src_idx,
                            const int*   __restrict__ dst_idx,
                            const float* __restrict__ edge_alpha,
                            const float* __restrict__ edge_w,
                            const float* __restrict__ edge_b,
                            int E) {
    int t = blockIdx.x * blockDim.x + threadIdx.x;
    if (t >= E * 4) return;
    int e = t >> 2;
    int q = t & 3;

    int   s  = src_idx[e];
    int   d  = dst_idx[e];
    float w  = edge_w[e];
    float bb = edge_b[e];
    float a  = edge_alpha[e];

    float4 xv = *(const float4*)&g_xt[s * B_DIM + 4 * q];

    float l0 = fmaf(w, xv.x, bb);
    float l1 = fmaf(w, xv.y, bb);
    float l2 = fmaf(w, xv.z, bb);
    float l3 = fmaf(w, xv.w, bb);

    float t0, t1, t2, t3;
    asm("tanh.approx.f32 %0, %1;" : "=f"(t0) : "f"(l0));
    asm("tanh.approx.f32 %0, %1;" : "=f"(t1) : "f"(l1));
    asm("tanh.approx.f32 %0, %1;" : "=f"(t2) : "f"(l2));
    asm("tanh.approx.f32 %0, %1;" : "=f"(t3) : "f"(l3));

    float m0 = fmaf(a, t0 - l0, l0);
    float m1 = fmaf(a, t1 - l1, l1);
    float m2 = fmaf(a, t2 - l2, l2);
    float m3 = fmaf(a, t3 - l3, l3);

    size_t gaddr = __cvta_generic_to_global(&g_yt[d * B_DIM + 4 * q]);
    asm volatile("red.global.add.v4.f32 [%0], {%1, %2, %3, %4};"
                 :: "l"(gaddr), "f"(m0), "f"(m1), "f"(m2), "f"(m3)
                 : "memory");
}

// ---------------------------------------------------------------------------
// Kernel 3: node stage + transpose back, float4 reads of g_yt.
// Tile: 64 nodes x 16 batches per block (256 threads).
// ---------------------------------------------------------------------------
__global__ void node_kernel(const float* __restrict__ node_alpha,
                            const float* __restrict__ node_w,
                            const float* __restrict__ node_b,
                            float* __restrict__ out, int N) {
    __shared__ float tile[16][67];
    int n0 = blockIdx.x * 64;
    int tid = threadIdx.x;

    // Load: thread -> (node, batch-quad), float4 coalesced read of g_yt.
    {
        int n = tid >> 2;
        int q = tid & 3;
        int nn = n0 + n;
        float4 v = make_float4(0.f, 0.f, 0.f, 0.f);
        if (nn < N) v = *(const float4*)&g_yt[nn * B_DIM + 4 * q];
        tile[4 * q + 0][n] = v.x;
        tile[4 * q + 1][n] = v.y;
        tile[4 * q + 2][n] = v.z;
        tile[4 * q + 3][n] = v.w;
    }
    __syncthreads();

    // Store: 4 passes, each covers 4 batch rows x 64 nodes, coalesced along n.
    #pragma unroll
    for (int p = 0; p < 4; p++) {
        int b = p * 4 + (tid >> 6);
        int n = tid & 63;
        int nn = n0 + n;
        if (nn < N) {
            float y   = tile[b][n];
            float w   = node_w[nn];
            float bb  = node_b[nn];
            float a   = node_alpha[nn];
            float lin = fmaf(w, y, bb);
            float th;
            asm("tanh.approx.f32 %0, %1;" : "=f"(th) : "f"(lin));
            out[b * N + nn] = fmaf(a, th - lin, lin);
        }
    }
}

// ---------------------------------------------------------------------------
// Input order: x, src_idx, dst_idx, edge_alpha, edge_w, edge_b,
// node_alpha, node_w, node_b. Output: float32 [B, N].
// ---------------------------------------------------------------------------
extern "C" void kernel_launch(void* const* d_in, const int* in_sizes, int n_in,
                              void* d_out, int out_size) {
    const float* x          = (const float*)d_in[0];
    const int*   src_idx    = (const int*)  d_in[1];
    const int*   dst_idx    = (const int*)  d_in[2];
    const float* edge_alpha = (const float*)d_in[3];
    const float* edge_w     = (const float*)d_in[4];
    const float* edge_b     = (const float*)d_in[5];
    const float* node_alpha = (const float*)d_in[6];
    const float* node_w     = (const float*)d_in[7];
    const float* node_b     = (const float*)d_in[8];
    float* out = (float*)d_out;

    const int E = in_sizes[1];
    const int N = in_sizes[6];

    int n_tiles = (N + 63) / 64;

    transpose_zero_kernel<<<n_tiles, 256>>>(x, N);

    int total = E * 4;
    int blocks = (total + 255) / 256;
    edge_kernel<<<blocks, 256>>>(src_idx, dst_idx, edge_alpha, edge_w, edge_b, E);

    node_kernel<<<n_tiles, 256>>>(node_alpha, node_w, node_b, out, N);
}